// round 13
// baseline (speedup 1.0000x reference)
#include <cuda_runtime.h>
#include <cstdint>

// LatentSpaceClustering: out[n] = argmin_k || x[n] - c[k] ||
// N = 1048576, H = 64, K = 256.
//
// Round-12 finding: output buffer is N x 4 bytes (int64 writes faulted) and the
// harness compares it as FLOAT32 (int32 index writes read back as denormals ~0,
// giving rel_err exactly 1.0 on every prior round). So: write (float)argmin.
//
// Engine: static 32KB smem center tile (2 passes of 128 centers), packed
// fma.rn.f32x2 (full-rate fp32 on sm_103a), 4 independent FMA chains, score
// d2 = (x2 + c2) - 2*dot in reference op order, top-2 + IEEE-sqrt tie resolve.

namespace {
constexpr int kN = 1048576;
constexpr int kH = 64;
constexpr int kK = 256;
constexpr int kHalfK = 128;
constexpr int kThreads = 256;
constexpr int kPtsPerBlock = 1024;
constexpr int kPtsPerThread = kPtsPerBlock / kThreads;  // 4
}  // namespace

__device__ __forceinline__ unsigned long long pack2f(float a, float b) {
    unsigned long long r;
    asm("mov.b64 %0, {%1, %2};" : "=l"(r) : "f"(a), "f"(b));
    return r;
}

// Packed dual-FMA: full-rate fp32 path on sm_103a.
__device__ __forceinline__ unsigned long long ffma2(unsigned long long a,
                                                    unsigned long long b,
                                                    unsigned long long c) {
    unsigned long long d;
    asm("fma.rn.f32x2 %0, %1, %2, %3;" : "=l"(d) : "l"(a), "l"(b), "l"(c));
    return d;
}

__device__ __forceinline__ float f2lo(unsigned long long v) {
    return __uint_as_float((unsigned int)v);
}
__device__ __forceinline__ float f2hi(unsigned long long v) {
    return __uint_as_float((unsigned int)(v >> 32));
}

__global__ __launch_bounds__(kThreads)
void lsc_assign_kernel(const float* __restrict__ x,
                       const float* __restrict__ c,
                       float* __restrict__ out) {
    __shared__ unsigned long long csh[kHalfK * kH / 2];  // 32 KB
    __shared__ float c2sh[kHalfK];

    const int tid = threadIdx.x;
    const int base = blockIdx.x * kPtsPerBlock + tid;

    // Top-2 tracking per point on raw d2.
    float s1a[kPtsPerThread], s2a[kPtsPerThread];
    int k1a[kPtsPerThread], k2a[kPtsPerThread];
    float x2a[kPtsPerThread];
    #pragma unroll
    for (int i = 0; i < kPtsPerThread; i++) {
        s1a[i] = 3.402823466e38f; s2a[i] = 3.402823466e38f;
        k1a[i] = 0; k2a[i] = 0;
    }

    const float4* xg = reinterpret_cast<const float4*>(x);

    // x2[n] = sum(x*x): mul then add (reference op order), ascending h.
    #pragma unroll
    for (int i = 0; i < kPtsPerThread; i++) {
        const int p = base + i * kThreads;
        float s = 0.0f;
        #pragma unroll
        for (int d4 = 0; d4 < kH / 4; d4++) {
            float4 v = xg[(size_t)p * (kH / 4) + d4];
            s = __fadd_rn(s, __fmul_rn(v.x, v.x));
            s = __fadd_rn(s, __fmul_rn(v.y, v.y));
            s = __fadd_rn(s, __fmul_rn(v.z, v.z));
            s = __fadd_rn(s, __fmul_rn(v.w, v.w));
        }
        x2a[i] = s;
    }

    for (int half = 0; half < 2; half++) {
        __syncthreads();

        // Stage this half's 128 centers (coalesced float4 copy).
        {
            const float4* cg4 = reinterpret_cast<const float4*>(c + half * kHalfK * kH);
            float4* cs4 = reinterpret_cast<float4*>(csh);
            for (int i = tid; i < kHalfK * kH / 4; i += kThreads) cs4[i] = cg4[i];
        }
        __syncthreads();

        // ||c_k||^2: mul then add, ascending h.
        if (tid < kHalfK) {
            const float* cf = reinterpret_cast<const float*>(csh);
            float s = 0.0f;
            #pragma unroll
            for (int d = 0; d < kH; d++) {
                float v = cf[tid * kH + d];
                s = __fadd_rn(s, __fmul_rn(v, v));
            }
            c2sh[tid] = s;
        }
        __syncthreads();

        for (int i = 0; i < kPtsPerThread; i++) {
            const int p = base + i * kThreads;

            // Point's 64 dims as 32 packed f32x2 registers.
            unsigned long long xp[kH / 2];
            #pragma unroll
            for (int d4 = 0; d4 < kH / 4; d4++) {
                float4 v = xg[(size_t)p * (kH / 4) + d4];
                xp[2 * d4 + 0] = pack2f(v.x, v.y);
                xp[2 * d4 + 1] = pack2f(v.z, v.w);
            }

            float s1 = s1a[i], s2 = s2a[i];
            int k1 = k1a[i], k2 = k2a[i];
            const float x2 = x2a[i];

            #pragma unroll 1
            for (int k0 = 0; k0 < kHalfK; k0 += 4) {
                // 4 centers -> 4 independent FMA chains (covers lat=4 @ rt=2).
                unsigned long long a0 = 0ull, a1 = 0ull, a2 = 0ull, a3 = 0ull;
                const ulonglong2* r0 = reinterpret_cast<const ulonglong2*>(csh + (k0 + 0) * (kH / 2));
                const ulonglong2* r1 = reinterpret_cast<const ulonglong2*>(csh + (k0 + 1) * (kH / 2));
                const ulonglong2* r2 = reinterpret_cast<const ulonglong2*>(csh + (k0 + 2) * (kH / 2));
                const ulonglong2* r3 = reinterpret_cast<const ulonglong2*>(csh + (k0 + 3) * (kH / 2));

                #pragma unroll
                for (int d4 = 0; d4 < kH / 4; d4++) {
                    // Broadcast LDS.128 (all lanes same address: conflict-free).
                    ulonglong2 q0 = r0[d4];
                    ulonglong2 q1 = r1[d4];
                    ulonglong2 q2 = r2[d4];
                    ulonglong2 q3 = r3[d4];
                    a0 = ffma2(q0.x, xp[2 * d4 + 0], a0);
                    a1 = ffma2(q1.x, xp[2 * d4 + 0], a1);
                    a2 = ffma2(q2.x, xp[2 * d4 + 0], a2);
                    a3 = ffma2(q3.x, xp[2 * d4 + 0], a3);
                    a0 = ffma2(q0.y, xp[2 * d4 + 1], a0);
                    a1 = ffma2(q1.y, xp[2 * d4 + 1], a1);
                    a2 = ffma2(q2.y, xp[2 * d4 + 1], a2);
                    a3 = ffma2(q3.y, xp[2 * d4 + 1], a3);
                }

                // d2 = (x2 + c2) - 2*dot, each op round-to-nearest.
                const int kg = half * kHalfK + k0;
                float d0 = __fadd_rn(f2lo(a0), f2hi(a0));
                float d1 = __fadd_rn(f2lo(a1), f2hi(a1));
                float d2 = __fadd_rn(f2lo(a2), f2hi(a2));
                float d3 = __fadd_rn(f2lo(a3), f2hi(a3));
                float t0 = __fadd_rn(x2, c2sh[k0 + 0]);
                float t1 = __fadd_rn(x2, c2sh[k0 + 1]);
                float t2 = __fadd_rn(x2, c2sh[k0 + 2]);
                float t3 = __fadd_rn(x2, c2sh[k0 + 3]);
                float v0 = __fadd_rn(t0, __fmul_rn(-2.0f, d0));
                float v1 = __fadd_rn(t1, __fmul_rn(-2.0f, d1));
                float v2 = __fadd_rn(t2, __fmul_rn(-2.0f, d2));
                float v3 = __fadd_rn(t3, __fmul_rn(-2.0f, d3));

                // Top-2 update, ascending k (first-index tie preference).
                if (v0 < s1) { s2 = s1; k2 = k1; s1 = v0; k1 = kg + 0; }
                else if (v0 < s2) { s2 = v0; k2 = kg + 0; }
                if (v1 < s1) { s2 = s1; k2 = k1; s1 = v1; k1 = kg + 1; }
                else if (v1 < s2) { s2 = v1; k2 = kg + 1; }
                if (v2 < s1) { s2 = s1; k2 = k1; s1 = v2; k1 = kg + 2; }
                else if (v2 < s2) { s2 = v2; k2 = kg + 2; }
                if (v3 < s1) { s2 = s1; k2 = k1; s1 = v3; k1 = kg + 3; }
                else if (v3 < s2) { s2 = v3; k2 = kg + 3; }
            }

            s1a[i] = s1; s2a[i] = s2; k1a[i] = k1; k2a[i] = k2;
        }
    }

    // Reference argmins over sqrt(max(d2,0)); on sqrt-tie keep the FIRST index.
    // OUTPUT AS FLOAT32: harness compares the N x 4B buffer as float.
    #pragma unroll
    for (int i = 0; i < kPtsPerThread; i++) {
        float r1 = __fsqrt_rn(fmaxf(s1a[i], 0.0f));
        float r2 = __fsqrt_rn(fmaxf(s2a[i], 0.0f));
        int ans = (r1 == r2) ? min(k1a[i], k2a[i]) : k1a[i];
        out[base + i * kThreads] = (float)ans;  // coalesced float stores
    }
}

extern "C" void kernel_launch(void* const* d_in, const int* in_sizes, int n_in,
                              void* d_out, int out_size) {
    const float* x = (const float*)d_in[0];
    const float* c = (const float*)d_in[1];
    // Defensive: if metadata ordering is reversed, detect by element counts.
    if (n_in >= 2 && in_sizes[0] == kK * kH && in_sizes[1] == kN * kH) {
        const float* t = x; x = c; c = t;
    }
    float* out = (float*)d_out;

    lsc_assign_kernel<<<kN / kPtsPerBlock, kThreads>>>(x, c, out);
}

// round 15
// speedup vs baseline: 3.2622x; 3.2622x over previous
#include <cuda_runtime.h>
#include <cstdint>

// LatentSpaceClustering: out[n] = (float) argmin_k || x[n] - c[k] ||
// N = 1048576, H = 64, K = 256. Output buffer is N float32 (round-13 finding).
//
// Round-14: kill the register spills. Round-13 ran at regs=255 (cap) with
// kPtsPerThread=4 -> LDL/STL spill traffic (L1 54.6%), occ 12.5%, fma 20%.
// Now ONE point per thread: xp (32 packed f32x2 regs) stays resident across
// both center halves, X is read from HBM exactly once, no spills.
// Arithmetic ordering is bit-identical to round 13 (rel_err 4.88e-4 preserved).

namespace {
constexpr int kN = 1048576;
constexpr int kH = 64;
constexpr int kK = 256;
constexpr int kHalfK = 128;
constexpr int kThreads = 256;
}  // namespace

__device__ __forceinline__ unsigned long long pack2f(float a, float b) {
    unsigned long long r;
    asm("mov.b64 %0, {%1, %2};" : "=l"(r) : "f"(a), "f"(b));
    return r;
}

// Packed dual-FMA: full-rate fp32 path on sm_103a (rt_SMSP=2, 2 FMA/instr).
__device__ __forceinline__ unsigned long long ffma2(unsigned long long a,
                                                    unsigned long long b,
                                                    unsigned long long c) {
    unsigned long long d;
    asm("fma.rn.f32x2 %0, %1, %2, %3;" : "=l"(d) : "l"(a), "l"(b), "l"(c));
    return d;
}

__device__ __forceinline__ float f2lo(unsigned long long v) {
    return __uint_as_float((unsigned int)v);
}
__device__ __forceinline__ float f2hi(unsigned long long v) {
    return __uint_as_float((unsigned int)(v >> 32));
}

__global__ __launch_bounds__(kThreads)
void lsc_assign_kernel(const float* __restrict__ x,
                       const float* __restrict__ c,
                       float* __restrict__ out) {
    __shared__ unsigned long long csh[kHalfK * kH / 2];  // 32 KB
    __shared__ float c2sh[kHalfK];

    const int tid = threadIdx.x;
    const int p = blockIdx.x * kThreads + tid;

    // ---- Load this thread's point ONCE; lives in registers for the whole kernel.
    unsigned long long xp[kH / 2];
    {
        const float4* xg = reinterpret_cast<const float4*>(x);
        #pragma unroll
        for (int d4 = 0; d4 < kH / 4; d4++) {
            float4 v = xg[(size_t)p * (kH / 4) + d4];
            xp[2 * d4 + 0] = pack2f(v.x, v.y);
            xp[2 * d4 + 1] = pack2f(v.z, v.w);
        }
    }

    // x2 = sum(x*x): mul then add, ascending h (same value order as round 13).
    float x2 = 0.0f;
    #pragma unroll
    for (int j = 0; j < kH / 2; j++) {
        x2 = __fadd_rn(x2, __fmul_rn(f2lo(xp[j]), f2lo(xp[j])));
        x2 = __fadd_rn(x2, __fmul_rn(f2hi(xp[j]), f2hi(xp[j])));
    }

    // Top-2 tracking on raw d2.
    float s1 = 3.402823466e38f, s2 = 3.402823466e38f;
    int k1 = 0, k2 = 0;

    for (int half = 0; half < 2; half++) {
        __syncthreads();  // previous pass's smem reads complete before overwrite

        // Stage this half's 128 centers (coalesced float4 copy: 8192 floats).
        {
            const float4* cg4 = reinterpret_cast<const float4*>(c + half * kHalfK * kH);
            float4* cs4 = reinterpret_cast<float4*>(csh);
            #pragma unroll
            for (int i = tid; i < kHalfK * kH / 4; i += kThreads) cs4[i] = cg4[i];
        }
        __syncthreads();

        // ||c_k||^2: mul then add, ascending h (threads 0..127).
        if (tid < kHalfK) {
            const float* cf = reinterpret_cast<const float*>(csh);
            float s = 0.0f;
            #pragma unroll
            for (int d = 0; d < kH; d++) {
                float v = cf[tid * kH + d];
                s = __fadd_rn(s, __fmul_rn(v, v));
            }
            c2sh[tid] = s;
        }
        __syncthreads();

        #pragma unroll 1
        for (int k0 = 0; k0 < kHalfK; k0 += 4) {
            // 4 centers -> 4 independent FMA chains (covers lat=4 @ rt=2).
            unsigned long long a0 = 0ull, a1 = 0ull, a2 = 0ull, a3 = 0ull;
            const ulonglong2* r0 = reinterpret_cast<const ulonglong2*>(csh + (k0 + 0) * (kH / 2));
            const ulonglong2* r1 = reinterpret_cast<const ulonglong2*>(csh + (k0 + 1) * (kH / 2));
            const ulonglong2* r2 = reinterpret_cast<const ulonglong2*>(csh + (k0 + 2) * (kH / 2));
            const ulonglong2* r3 = reinterpret_cast<const ulonglong2*>(csh + (k0 + 3) * (kH / 2));

            #pragma unroll
            for (int d4 = 0; d4 < kH / 4; d4++) {
                // Broadcast LDS.128 (all lanes same address: conflict-free).
                ulonglong2 q0 = r0[d4];
                ulonglong2 q1 = r1[d4];
                ulonglong2 q2 = r2[d4];
                ulonglong2 q3 = r3[d4];
                a0 = ffma2(q0.x, xp[2 * d4 + 0], a0);
                a1 = ffma2(q1.x, xp[2 * d4 + 0], a1);
                a2 = ffma2(q2.x, xp[2 * d4 + 0], a2);
                a3 = ffma2(q3.x, xp[2 * d4 + 0], a3);
                a0 = ffma2(q0.y, xp[2 * d4 + 1], a0);
                a1 = ffma2(q1.y, xp[2 * d4 + 1], a1);
                a2 = ffma2(q2.y, xp[2 * d4 + 1], a2);
                a3 = ffma2(q3.y, xp[2 * d4 + 1], a3);
            }

            // d2 = (x2 + c2) - 2*dot, each op round-to-nearest (round-13 order).
            const int kg = half * kHalfK + k0;
            float d0 = __fadd_rn(f2lo(a0), f2hi(a0));
            float d1 = __fadd_rn(f2lo(a1), f2hi(a1));
            float d2 = __fadd_rn(f2lo(a2), f2hi(a2));
            float d3 = __fadd_rn(f2lo(a3), f2hi(a3));
            float t0 = __fadd_rn(x2, c2sh[k0 + 0]);
            float t1 = __fadd_rn(x2, c2sh[k0 + 1]);
            float t2 = __fadd_rn(x2, c2sh[k0 + 2]);
            float t3 = __fadd_rn(x2, c2sh[k0 + 3]);
            float v0 = __fadd_rn(t0, __fmul_rn(-2.0f, d0));
            float v1 = __fadd_rn(t1, __fmul_rn(-2.0f, d1));
            float v2 = __fadd_rn(t2, __fmul_rn(-2.0f, d2));
            float v3 = __fadd_rn(t3, __fmul_rn(-2.0f, d3));

            // Top-2 update, ascending k (first-index tie preference).
            if (v0 < s1) { s2 = s1; k2 = k1; s1 = v0; k1 = kg + 0; }
            else if (v0 < s2) { s2 = v0; k2 = kg + 0; }
            if (v1 < s1) { s2 = s1; k2 = k1; s1 = v1; k1 = kg + 1; }
            else if (v1 < s2) { s2 = v1; k2 = kg + 1; }
            if (v2 < s1) { s2 = s1; k2 = k1; s1 = v2; k1 = kg + 2; }
            else if (v2 < s2) { s2 = v2; k2 = kg + 2; }
            if (v3 < s1) { s2 = s1; k2 = k1; s1 = v3; k1 = kg + 3; }
            else if (v3 < s2) { s2 = v3; k2 = kg + 3; }
        }
    }

    // Reference argmins over sqrt(max(d2,0)); on sqrt-tie keep the FIRST index.
    float r1 = __fsqrt_rn(fmaxf(s1, 0.0f));
    float r2 = __fsqrt_rn(fmaxf(s2, 0.0f));
    int ans = (r1 == r2) ? min(k1, k2) : k1;
    out[p] = (float)ans;  // coalesced float stores
}

extern "C" void kernel_launch(void* const* d_in, const int* in_sizes, int n_in,
                              void* d_out, int out_size) {
    const float* x = (const float*)d_in[0];
    const float* c = (const float*)d_in[1];
    // Defensive: if metadata ordering is reversed, detect by element counts.
    if (n_in >= 2 && in_sizes[0] == kK * kH && in_sizes[1] == kN * kH) {
        const float* t = x; x = c; c = t;
    }
    float* out = (float*)d_out;

    lsc_assign_kernel<<<kN / kThreads, kThreads>>>(x, c, out);
}

// round 16
// speedup vs baseline: 4.2578x; 1.3052x over previous
#include <cuda_runtime.h>
#include <cstdint>

// LatentSpaceClustering: out[n] = (float) argmin_k || x[n] - c[k] ||
// N = 1048576, H = 64, K = 256. Output: N float32 (indices as floats).
//
// Round-15: LDS-issue was co-binding with FMA (both ~477us of demand; L1 86%).
// Amortize each broadcast LDS.128 over TWO points per thread: FMA:LDS ratio
// 2:1 -> 4:1, LDS demand halves, FMA becomes the binding pipe.
// Register budget: xp 64 + q 16 + acc 8 + state 12 + misc ~= 170 (no spill).
// Per-point arithmetic order unchanged -> rel_err bit-identical (4.876e-4).

namespace {
constexpr int kN = 1048576;
constexpr int kH = 64;
constexpr int kK = 256;
constexpr int kHalfK = 128;
constexpr int kThreads = 256;
constexpr int kPtsPerThread = 2;
constexpr int kPtsPerBlock = kThreads * kPtsPerThread;  // 512
}  // namespace

__device__ __forceinline__ unsigned long long pack2f(float a, float b) {
    unsigned long long r;
    asm("mov.b64 %0, {%1, %2};" : "=l"(r) : "f"(a), "f"(b));
    return r;
}

// Packed dual-FMA: full-rate fp32 path on sm_103a (rt_SMSP=2, 2 FMA/instr).
__device__ __forceinline__ unsigned long long ffma2(unsigned long long a,
                                                    unsigned long long b,
                                                    unsigned long long c) {
    unsigned long long d;
    asm("fma.rn.f32x2 %0, %1, %2, %3;" : "=l"(d) : "l"(a), "l"(b), "l"(c));
    return d;
}

__device__ __forceinline__ float f2lo(unsigned long long v) {
    return __uint_as_float((unsigned int)v);
}
__device__ __forceinline__ float f2hi(unsigned long long v) {
    return __uint_as_float((unsigned int)(v >> 32));
}

__global__ __launch_bounds__(kThreads)
void lsc_assign_kernel(const float* __restrict__ x,
                       const float* __restrict__ c,
                       float* __restrict__ out) {
    __shared__ unsigned long long csh[kHalfK * kH / 2];  // 32 KB
    __shared__ float c2sh[kHalfK];

    const int tid = threadIdx.x;
    const int p0 = blockIdx.x * kPtsPerBlock + tid;            // point A
    const int p1 = p0 + kThreads;                              // point B

    // ---- Both points' 64 dims resident in registers for the whole kernel.
    unsigned long long xa[kH / 2], xb[kH / 2];
    {
        const float4* xg = reinterpret_cast<const float4*>(x);
        #pragma unroll
        for (int d4 = 0; d4 < kH / 4; d4++) {
            float4 v = xg[(size_t)p0 * (kH / 4) + d4];
            xa[2 * d4 + 0] = pack2f(v.x, v.y);
            xa[2 * d4 + 1] = pack2f(v.z, v.w);
        }
        #pragma unroll
        for (int d4 = 0; d4 < kH / 4; d4++) {
            float4 v = xg[(size_t)p1 * (kH / 4) + d4];
            xb[2 * d4 + 0] = pack2f(v.x, v.y);
            xb[2 * d4 + 1] = pack2f(v.z, v.w);
        }
    }

    // x2 = sum(x*x): mul then add, ascending h (reference op order).
    float x2a = 0.0f, x2b = 0.0f;
    #pragma unroll
    for (int j = 0; j < kH / 2; j++) {
        x2a = __fadd_rn(x2a, __fmul_rn(f2lo(xa[j]), f2lo(xa[j])));
        x2a = __fadd_rn(x2a, __fmul_rn(f2hi(xa[j]), f2hi(xa[j])));
    }
    #pragma unroll
    for (int j = 0; j < kH / 2; j++) {
        x2b = __fadd_rn(x2b, __fmul_rn(f2lo(xb[j]), f2lo(xb[j])));
        x2b = __fadd_rn(x2b, __fmul_rn(f2hi(xb[j]), f2hi(xb[j])));
    }

    // Top-2 tracking per point on raw d2.
    float s1A = 3.402823466e38f, s2A = 3.402823466e38f;
    float s1B = 3.402823466e38f, s2B = 3.402823466e38f;
    int k1A = 0, k2A = 0, k1B = 0, k2B = 0;

    for (int half = 0; half < 2; half++) {
        __syncthreads();

        // Stage this half's 128 centers (coalesced float4 copy).
        {
            const float4* cg4 = reinterpret_cast<const float4*>(c + half * kHalfK * kH);
            float4* cs4 = reinterpret_cast<float4*>(csh);
            #pragma unroll
            for (int i = tid; i < kHalfK * kH / 4; i += kThreads) cs4[i] = cg4[i];
        }
        __syncthreads();

        // ||c_k||^2: mul then add, ascending h (threads 0..127).
        if (tid < kHalfK) {
            const float* cf = reinterpret_cast<const float*>(csh);
            float s = 0.0f;
            #pragma unroll
            for (int d = 0; d < kH; d++) {
                float v = cf[tid * kH + d];
                s = __fadd_rn(s, __fmul_rn(v, v));
            }
            c2sh[tid] = s;
        }
        __syncthreads();

        #pragma unroll 1
        for (int k0 = 0; k0 < kHalfK; k0 += 4) {
            // 4 centers x 2 points -> 8 independent FMA chains per loaded quad.
            unsigned long long a0 = 0ull, a1 = 0ull, a2 = 0ull, a3 = 0ull;
            unsigned long long b0 = 0ull, b1 = 0ull, b2 = 0ull, b3 = 0ull;
            const ulonglong2* r0 = reinterpret_cast<const ulonglong2*>(csh + (k0 + 0) * (kH / 2));
            const ulonglong2* r1 = reinterpret_cast<const ulonglong2*>(csh + (k0 + 1) * (kH / 2));
            const ulonglong2* r2 = reinterpret_cast<const ulonglong2*>(csh + (k0 + 2) * (kH / 2));
            const ulonglong2* r3 = reinterpret_cast<const ulonglong2*>(csh + (k0 + 3) * (kH / 2));

            #pragma unroll
            for (int d4 = 0; d4 < kH / 4; d4++) {
                // Broadcast LDS.128 (conflict-free), reused by both points.
                ulonglong2 q0 = r0[d4];
                ulonglong2 q1 = r1[d4];
                ulonglong2 q2 = r2[d4];
                ulonglong2 q3 = r3[d4];
                a0 = ffma2(q0.x, xa[2 * d4 + 0], a0);
                a1 = ffma2(q1.x, xa[2 * d4 + 0], a1);
                a2 = ffma2(q2.x, xa[2 * d4 + 0], a2);
                a3 = ffma2(q3.x, xa[2 * d4 + 0], a3);
                b0 = ffma2(q0.x, xb[2 * d4 + 0], b0);
                b1 = ffma2(q1.x, xb[2 * d4 + 0], b1);
                b2 = ffma2(q2.x, xb[2 * d4 + 0], b2);
                b3 = ffma2(q3.x, xb[2 * d4 + 0], b3);
                a0 = ffma2(q0.y, xa[2 * d4 + 1], a0);
                a1 = ffma2(q1.y, xa[2 * d4 + 1], a1);
                a2 = ffma2(q2.y, xa[2 * d4 + 1], a2);
                a3 = ffma2(q3.y, xa[2 * d4 + 1], a3);
                b0 = ffma2(q0.y, xb[2 * d4 + 1], b0);
                b1 = ffma2(q1.y, xb[2 * d4 + 1], b1);
                b2 = ffma2(q2.y, xb[2 * d4 + 1], b2);
                b3 = ffma2(q3.y, xb[2 * d4 + 1], b3);
            }

            const int kg = half * kHalfK + k0;
            const float c20 = c2sh[k0 + 0];
            const float c21 = c2sh[k0 + 1];
            const float c22 = c2sh[k0 + 2];
            const float c23 = c2sh[k0 + 3];

            // Point A: d2 = (x2 + c2) - 2*dot, reference op order.
            {
                float d0 = __fadd_rn(f2lo(a0), f2hi(a0));
                float d1 = __fadd_rn(f2lo(a1), f2hi(a1));
                float d2 = __fadd_rn(f2lo(a2), f2hi(a2));
                float d3 = __fadd_rn(f2lo(a3), f2hi(a3));
                float v0 = __fadd_rn(__fadd_rn(x2a, c20), __fmul_rn(-2.0f, d0));
                float v1 = __fadd_rn(__fadd_rn(x2a, c21), __fmul_rn(-2.0f, d1));
                float v2 = __fadd_rn(__fadd_rn(x2a, c22), __fmul_rn(-2.0f, d2));
                float v3 = __fadd_rn(__fadd_rn(x2a, c23), __fmul_rn(-2.0f, d3));
                if (v0 < s1A) { s2A = s1A; k2A = k1A; s1A = v0; k1A = kg + 0; }
                else if (v0 < s2A) { s2A = v0; k2A = kg + 0; }
                if (v1 < s1A) { s2A = s1A; k2A = k1A; s1A = v1; k1A = kg + 1; }
                else if (v1 < s2A) { s2A = v1; k2A = kg + 1; }
                if (v2 < s1A) { s2A = s1A; k2A = k1A; s1A = v2; k1A = kg + 2; }
                else if (v2 < s2A) { s2A = v2; k2A = kg + 2; }
                if (v3 < s1A) { s2A = s1A; k2A = k1A; s1A = v3; k1A = kg + 3; }
                else if (v3 < s2A) { s2A = v3; k2A = kg + 3; }
            }
            // Point B.
            {
                float d0 = __fadd_rn(f2lo(b0), f2hi(b0));
                float d1 = __fadd_rn(f2lo(b1), f2hi(b1));
                float d2 = __fadd_rn(f2lo(b2), f2hi(b2));
                float d3 = __fadd_rn(f2lo(b3), f2hi(b3));
                float v0 = __fadd_rn(__fadd_rn(x2b, c20), __fmul_rn(-2.0f, d0));
                float v1 = __fadd_rn(__fadd_rn(x2b, c21), __fmul_rn(-2.0f, d1));
                float v2 = __fadd_rn(__fadd_rn(x2b, c22), __fmul_rn(-2.0f, d2));
                float v3 = __fadd_rn(__fadd_rn(x2b, c23), __fmul_rn(-2.0f, d3));
                if (v0 < s1B) { s2B = s1B; k2B = k1B; s1B = v0; k1B = kg + 0; }
                else if (v0 < s2B) { s2B = v0; k2B = kg + 0; }
                if (v1 < s1B) { s2B = s1B; k2B = k1B; s1B = v1; k1B = kg + 1; }
                else if (v1 < s2B) { s2B = v1; k2B = kg + 1; }
                if (v2 < s1B) { s2B = s1B; k2B = k1B; s1B = v2; k1B = kg + 2; }
                else if (v2 < s2B) { s2B = v2; k2B = kg + 2; }
                if (v3 < s1B) { s2B = s1B; k2B = k1B; s1B = v3; k1B = kg + 3; }
                else if (v3 < s2B) { s2B = v3; k2B = kg + 3; }
            }
        }
    }

    // Reference argmins over sqrt(max(d2,0)); on sqrt-tie keep FIRST index.
    {
        float r1 = __fsqrt_rn(fmaxf(s1A, 0.0f));
        float r2 = __fsqrt_rn(fmaxf(s2A, 0.0f));
        int ans = (r1 == r2) ? min(k1A, k2A) : k1A;
        out[p0] = (float)ans;
    }
    {
        float r1 = __fsqrt_rn(fmaxf(s1B, 0.0f));
        float r2 = __fsqrt_rn(fmaxf(s2B, 0.0f));
        int ans = (r1 == r2) ? min(k1B, k2B) : k1B;
        out[p1] = (float)ans;
    }
}

extern "C" void kernel_launch(void* const* d_in, const int* in_sizes, int n_in,
                              void* d_out, int out_size) {
    const float* x = (const float*)d_in[0];
    const float* c = (const float*)d_in[1];
    // Defensive: if metadata ordering is reversed, detect by element counts.
    if (n_in >= 2 && in_sizes[0] == kK * kH && in_sizes[1] == kN * kH) {
        const float* t = x; x = c; c = t;
    }
    float* out = (float*)d_out;

    lsc_assign_kernel<<<kN / kPtsPerBlock, kThreads>>>(x, c, out);
}